// round 7
// baseline (speedup 1.0000x reference)
#include <cuda_runtime.h>
#include <cuda_bf16.h>

// Welford running mean/variance over batch dim of x: (B, C, H, W), B=256, CHW=262144.
// One scalar thread per spatial position (262,144 threads), exact sequential Welford.
//
// R7: true MLP=4 with minimal register cost. Four persistent load pointers and four
// persistent store pointers (incremented by 4*CHW per outer step) keep the 4 batched
// LDGs genuinely independent in SASS without per-iteration address recomputation.
// __launch_bounds__(256, 6) caps regs at 42 -> 1536 thr/SM (48 warps, ~R1 residency).
//
// Output layout (float32, concatenated):
//   [0, B*CHW)     : x passthrough
//   [+0, +CHW)     : m
//   [+CHW, +2CHW)  : s
//   [+2CHW, +3CHW) : neuron_nonzero (int -> float)
//   [last]         : n_samples + B

__global__ void __launch_bounds__(256, 6) welford_kernel_p4(
    const float* __restrict__ x,
    const float* __restrict__ m_in,
    const float* __restrict__ s_in,
    const int*   __restrict__ nn_in,
    const int*   __restrict__ n_in,
    float*       __restrict__ out,
    int B, int CHW)
{
    int p = blockIdx.x * blockDim.x + threadIdx.x;
    if (p >= CHW) return;

    float m  = m_in[p];
    float s  = s_in[p];
    int   nn = nn_in[p];
    const int n0 = n_in[0];

    // Persistent, independently-incremented pointers (4 load + 4 store).
    const size_t step = (size_t)CHW;
    const float* a0 = x + p;
    const float* a1 = a0 + step;
    const float* a2 = a1 + step;
    const float* a3 = a2 + step;
    float* o0 = out + p;
    float* o1 = o0 + step;
    float* o2 = o1 + step;
    float* o3 = o2 + step;
    const size_t bump = 4 * step;

    float nf = (float)n0;   // running sample count as float (exact: small ints)

    for (int b = 0; b < B; b += 4) {
        // Phase 1: 4 independent loads (distinct regs, distinct persistent addrs).
        float v0 = *a0;
        float v1 = *a1;
        float v2 = *a2;
        float v3 = *a3;

        // Phase 2: passthrough stores.
        *o0 = v0;
        *o1 = v1;
        *o2 = v2;
        *o3 = v3;

        a0 += bump; a1 += bump; a2 += bump; a3 += bump;
        o0 += bump; o1 += bump; o2 += bump; o3 += bump;

        // Phase 3: exact sequential Welford (same numerics as reference).
        float om, inv;

        nn += (v0 != 0.0f);
        inv = __fdividef(1.0f, nf + 1.0f);
        om = m; m += (v0 - m) * inv; s += (v0 - m) * (v0 - om);

        nn += (v1 != 0.0f);
        inv = __fdividef(1.0f, nf + 2.0f);
        om = m; m += (v1 - m) * inv; s += (v1 - m) * (v1 - om);

        nn += (v2 != 0.0f);
        inv = __fdividef(1.0f, nf + 3.0f);
        om = m; m += (v2 - m) * inv; s += (v2 - m) * (v2 - om);

        nn += (v3 != 0.0f);
        inv = __fdividef(1.0f, nf + 4.0f);
        om = m; m += (v3 - m) * inv; s += (v3 - m) * (v3 - om);

        nf += 4.0f;
    }

    size_t base = (size_t)B * (size_t)CHW;
    out[base + p]                   = m;
    out[base + (size_t)CHW + p]     = s;
    out[base + 2 * (size_t)CHW + p] = (float)nn;
    if (p == 0) {
        out[base + 3 * (size_t)CHW] = (float)(n0 + B);
    }
}

extern "C" void kernel_launch(void* const* d_in, const int* in_sizes, int n_in,
                              void* d_out, int out_size)
{
    const float* x  = (const float*)d_in[0];
    const float* m  = (const float*)d_in[1];
    const float* s  = (const float*)d_in[2];
    const int*   nn = (const int*)d_in[3];
    const int*   n  = (const int*)d_in[4];
    float* out = (float*)d_out;

    const int CHW = in_sizes[1];          // 262144
    const int B   = in_sizes[0] / CHW;    // 256

    const int threads = 256;
    const int blocks = (CHW + threads - 1) / threads;  // 1024
    welford_kernel_p4<<<blocks, threads>>>(x, m, s, nn, n, out, B, CHW);
}

// round 8
// speedup vs baseline: 1.2400x; 1.2400x over previous
#include <cuda_runtime.h>
#include <cuda_bf16.h>

// Welford running mean/variance over batch dim of x: (B, C, H, W), B=256, CHW=262144.
// One scalar thread per spatial position; exact sequential Welford (reference numerics).
//
// R8: SOFTWARE PIPELINE. Every prior round ran at true MLP=1 because ptxas interleaves
// LDG/STG of the same value, stalling 577 cyc at each store. Here, each loop body FIRST
// issues 4 loads for batch k+1 (independent regs), THEN stores/consumes batch k (whose
// data arrived an iteration ago). Loads precede all scoreboard waits in program order
// -> steady-state MLP~4 -> supply ~85 B/cyc/SM >> HBM ceiling (~30) -> HBM-bound.
//
// Output layout (float32, concatenated):
//   [0, B*CHW) : x passthrough | [+0,+CHW): m | [+CHW,+2CHW): s
//   [+2CHW,+3CHW): neuron_nonzero | [last]: n_samples + B

__global__ void __launch_bounds__(256, 6) welford_pipe(
    const float* __restrict__ x,
    const float* __restrict__ m_in,
    const float* __restrict__ s_in,
    const int*   __restrict__ nn_in,
    const int*   __restrict__ n_in,
    float*       __restrict__ out,
    int B, int CHW)
{
    int p = blockIdx.x * blockDim.x + threadIdx.x;
    if (p >= CHW) return;

    float m  = m_in[p];
    float s  = s_in[p];
    int   nn = nn_in[p];
    const int n0 = n_in[0];
    float nf = (float)n0;

    const size_t step = (size_t)CHW;

    // Prologue: prefetch batch 0.
    size_t off = (size_t)p;
    float v0 = x[off];
    float v1 = x[off +     step];
    float v2 = x[off + 2 * step];
    float v3 = x[off + 3 * step];

    // Main loop: (B/4 - 1) iterations, each prefetches the NEXT batch before
    // consuming the current one.
    for (int b = 0; b < B - 4; b += 4) {
        size_t noff = off + 4 * step;

        // Phase 1: issue next-batch loads (no dependence on anything pending).
        float w0 = x[noff];
        float w1 = x[noff +     step];
        float w2 = x[noff + 2 * step];
        float w3 = x[noff + 3 * step];

        // Phase 2: store + Welford on current batch (data arrived last iteration).
        out[off]            = v0;
        out[off +     step] = v1;
        out[off + 2 * step] = v2;
        out[off + 3 * step] = v3;

        float om, inv;
        nn += (v0 != 0.0f);
        inv = __fdividef(1.0f, nf + 1.0f);
        om = m; m += (v0 - m) * inv; s += (v0 - m) * (v0 - om);
        nn += (v1 != 0.0f);
        inv = __fdividef(1.0f, nf + 2.0f);
        om = m; m += (v1 - m) * inv; s += (v1 - m) * (v1 - om);
        nn += (v2 != 0.0f);
        inv = __fdividef(1.0f, nf + 3.0f);
        om = m; m += (v2 - m) * inv; s += (v2 - m) * (v2 - om);
        nn += (v3 != 0.0f);
        inv = __fdividef(1.0f, nf + 4.0f);
        om = m; m += (v3 - m) * inv; s += (v3 - m) * (v3 - om);
        nf += 4.0f;

        // Rotate pipeline registers.
        v0 = w0; v1 = w1; v2 = w2; v3 = w3;
        off = noff;
    }

    // Epilogue: final batch (no prefetch).
    {
        out[off]            = v0;
        out[off +     step] = v1;
        out[off + 2 * step] = v2;
        out[off + 3 * step] = v3;

        float om, inv;
        nn += (v0 != 0.0f);
        inv = __fdividef(1.0f, nf + 1.0f);
        om = m; m += (v0 - m) * inv; s += (v0 - m) * (v0 - om);
        nn += (v1 != 0.0f);
        inv = __fdividef(1.0f, nf + 2.0f);
        om = m; m += (v1 - m) * inv; s += (v1 - m) * (v1 - om);
        nn += (v2 != 0.0f);
        inv = __fdividef(1.0f, nf + 3.0f);
        om = m; m += (v2 - m) * inv; s += (v2 - m) * (v2 - om);
        nn += (v3 != 0.0f);
        inv = __fdividef(1.0f, nf + 4.0f);
        om = m; m += (v3 - m) * inv; s += (v3 - m) * (v3 - om);
    }

    size_t base = (size_t)B * (size_t)CHW;
    out[base + p]                   = m;
    out[base + (size_t)CHW + p]     = s;
    out[base + 2 * (size_t)CHW + p] = (float)nn;
    if (p == 0) {
        out[base + 3 * (size_t)CHW] = (float)(n0 + B);
    }
}

extern "C" void kernel_launch(void* const* d_in, const int* in_sizes, int n_in,
                              void* d_out, int out_size)
{
    const float* x  = (const float*)d_in[0];
    const float* m  = (const float*)d_in[1];
    const float* s  = (const float*)d_in[2];
    const int*   nn = (const int*)d_in[3];
    const int*   n  = (const int*)d_in[4];
    float* out = (float*)d_out;

    const int CHW = in_sizes[1];          // 262144
    const int B   = in_sizes[0] / CHW;    // 256

    const int threads = 256;
    const int blocks = (CHW + threads - 1) / threads;  // 1024
    welford_pipe<<<blocks, threads>>>(x, m, s, nn, n, out, B, CHW);
}